// round 16
// baseline (speedup 1.0000x reference)
#include <cuda_runtime.h>
#include <cuda_fp16.h>
#include <cstdint>
#include <math.h>

// ---------------- problem constants ----------------
#define BATCH 8
#define LEN   4096
#define INP   1024
#define STATE 512
#define KHALF 256
#define OUTD  1024
#define ROWS  (BATCH*LEN)      // 32768
#define HROWS (ROWS/2)         // 16384 (batch half)
#define HBATCH (BATCH/2)
#define CHUNK 32
#define NCHUNK (LEN/CHUNK)     // 128
#define LOG2CHUNK 5
#define EPSV 1e-6f

// ---------------- scratch (device globals; no runtime allocation) ----------------
__device__ __half g_uh[(size_t)ROWS * INP];      // rmsnormed u, fp16
__device__ __half g_uB[(size_t)ROWS * STATE];    // un @ B, fp16
__device__ __half g_xh[(size_t)ROWS * STATE];    // scan output, fp16
__device__ __half g_Bt[(size_t)STATE * INP];     // B^T  (512 x 1024)
__device__ __half g_Ct[(size_t)OUTD  * STATE];   // C^T  (1024 x 512)
__device__ float2 g_localF[BATCH * NCHUNK * KHALF];
__device__ float2 g_carry [BATCH * NCHUNK * KHALF];

// ---------------- one-time stream/event objects (host-side, pre-main) ----------
struct AuxStreams {
    cudaStream_t s1;
    cudaEvent_t eStart, eT, eC0, eEnd;
    AuxStreams() {
        cudaStreamCreateWithFlags(&s1, cudaStreamNonBlocking);
        cudaEventCreateWithFlags(&eStart, cudaEventDisableTiming);
        cudaEventCreateWithFlags(&eT,     cudaEventDisableTiming);
        cudaEventCreateWithFlags(&eC0,    cudaEventDisableTiming);
        cudaEventCreateWithFlags(&eEnd,   cudaEventDisableTiming);
    }
};
static AuxStreams g_aux;

// ---------------- helpers ----------------
__device__ __forceinline__ uint32_t smem_u32(const void* p) {
    uint32_t a;
    asm("{ .reg .u64 t; cvta.to.shared.u64 t, %1; cvt.u32.u64 %0, t; }" : "=r"(a) : "l"(p));
    return a;
}
__device__ __forceinline__ void cp16(uint32_t dst, const void* src) {
    asm volatile("cp.async.cg.shared.global [%0], [%1], 16;" :: "r"(dst), "l"(src));
}
__device__ __forceinline__ void cp_commit() { asm volatile("cp.async.commit_group;"); }
template <int N> __device__ __forceinline__ void cp_wait() {
    asm volatile("cp.async.wait_group %0;" :: "n"(N));
}
__device__ __forceinline__ void ldsm_x4(uint32_t* r, uint32_t addr) {
    asm volatile("ldmatrix.sync.aligned.m8n8.x4.shared.b16 {%0,%1,%2,%3}, [%4];"
                 : "=r"(r[0]), "=r"(r[1]), "=r"(r[2]), "=r"(r[3]) : "r"(addr));
}
__device__ __forceinline__ void mma16816(float* c, const uint32_t* a, const uint32_t* b) {
    asm volatile("mma.sync.aligned.m16n8k16.row.col.f32.f16.f16.f32 "
                 "{%0,%1,%2,%3}, {%4,%5,%6,%7}, {%8,%9}, {%0,%1,%2,%3};"
                 : "+f"(c[0]), "+f"(c[1]), "+f"(c[2]), "+f"(c[3])
                 : "r"(a[0]), "r"(a[1]), "r"(a[2]), "r"(a[3]), "r"(b[0]), "r"(b[1]));
}

// ---------------- complex helpers ----------------
__device__ __forceinline__ float2 cmul(float2 a, float2 b) {
    return make_float2(a.x * b.x - a.y * b.y, a.x * b.y + a.y * b.x);
}
__device__ __forceinline__ float2 cmad(float2 a, float2 z, float2 w) {
    return make_float2(fmaf(a.x, z.x, fmaf(-a.y, z.y, w.x)),
                       fmaf(a.x, z.y, fmaf( a.y, z.x, w.y)));
}

// ---------------- prep: fused rmsnorm -> fp16 u (warp-per-row) ----------------
__global__ void __launch_bounds__(256)
convert_u_kernel(const float* __restrict__ u, const float* __restrict__ nw, int row0) {
    const int row  = row0 + blockIdx.x * 8 + (threadIdx.x >> 5);
    const int lane = threadIdx.x & 31;
    const float4* up = reinterpret_cast<const float4*>(u) + (size_t)row * 256;
    float4 v[8];
    float s = 0.f;
    #pragma unroll
    for (int i = 0; i < 8; i++) {
        v[i] = __ldcs(up + lane + i * 32);
        s += v[i].x * v[i].x + v[i].y * v[i].y + v[i].z * v[i].z + v[i].w * v[i].w;
    }
    #pragma unroll
    for (int o = 16; o; o >>= 1) s += __shfl_xor_sync(0xffffffffu, s, o);
    const float rs = rsqrtf(s * (1.0f / INP) + EPSV);
    const float4* nwp = reinterpret_cast<const float4*>(nw);
    __half2* uh2 = reinterpret_cast<__half2*>(g_uh) + (size_t)row * 512;
    #pragma unroll
    for (int i = 0; i < 8; i++) {
        float4 w = nwp[lane + i * 32];
        int e = (lane + i * 32) * 2;
        uh2[e]     = __floats2half2_rn(v[i].x * rs * w.x, v[i].y * rs * w.y);
        uh2[e + 1] = __floats2half2_rn(v[i].z * rs * w.z, v[i].w * rs * w.w);
    }
}

// ---------------- prep: smem-tiled transpose float[M,N] -> half[N,M] ----------------
__global__ void __launch_bounds__(256)
transpose_kernel(const float* __restrict__ src, __half* __restrict__ dst,
                 int M, int N) {
    __shared__ float tile[32][33];
    const int n0 = blockIdx.x * 32;
    const int m0 = blockIdx.y * 32;
    #pragma unroll
    for (int i = 0; i < 4; i++) {
        int m = m0 + threadIdx.y + i * 8;
        tile[threadIdx.y + i * 8][threadIdx.x] = src[(size_t)m * N + n0 + threadIdx.x];
    }
    __syncthreads();
    #pragma unroll
    for (int i = 0; i < 4; i++) {
        int n = n0 + threadIdx.y + i * 8;
        dst[(size_t)n * M + m0 + threadIdx.x] =
            __float2half_rn(tile[threadIdx.x][threadIdx.y + i * 8]);
    }
}

// ---------------- HGEMM: C[M,N] = A[M,K](f16) x Bt[N,K](f16)^T ----------------
#define KCH     64
#define PITCH   144
#define STG_A   (128 * PITCH)
#define STG_SZ  (2 * STG_A)
#define NSTAGE  3
#define SM_TOT  (NSTAGE * STG_SZ)

__device__ __forceinline__ void load_stage(uint32_t sbase, int s, int c, int tid,
                                           const __half* __restrict__ Ag,
                                           const __half* __restrict__ Bg,
                                           int m0, int n0, int K) {
    const uint32_t sa = sbase + (uint32_t)s * STG_SZ;
    const uint32_t sb = sa + STG_A;
    #pragma unroll
    for (int i = 0; i < 4; i++) {
        int lin = tid + i * 256;
        int row = lin >> 3, ch = lin & 7;
        cp16(sa + row * PITCH + ch * 16, Ag + (size_t)(m0 + row) * K + c * KCH + ch * 8);
        cp16(sb + row * PITCH + ch * 16, Bg + (size_t)(n0 + row) * K + c * KCH + ch * 8);
    }
}

template <bool HALF_OUT>
__global__ void __launch_bounds__(256, 2)
hgemm_kernel(const __half* __restrict__ Ag, const __half* __restrict__ Bg,
             void* __restrict__ CoutV, int K, int N, int moff) {
    extern __shared__ char smem[];
    const uint32_t sbase = smem_u32(smem);
    const int tid  = threadIdx.x;
    const int lane = tid & 31;
    const int wid  = tid >> 5;
    const int wm   = (wid & 1) * 64;
    const int wn   = (wid >> 1) * 32;
    const int m0   = moff + blockIdx.y * 128;
    const int n0   = blockIdx.x * 128;
    const int NC   = K / KCH;

    float acc[4][4][4];
    #pragma unroll
    for (int i = 0; i < 4; i++)
        #pragma unroll
        for (int j = 0; j < 4; j++)
            #pragma unroll
            for (int q = 0; q < 4; q++) acc[i][j][q] = 0.f;

    load_stage(sbase, 0, 0, tid, Ag, Bg, m0, n0, K); cp_commit();
    load_stage(sbase, 1, 1, tid, Ag, Bg, m0, n0, K); cp_commit();

    for (int c = 0; c < NC; c++) {
        const int s = c % NSTAGE;
        if (c + 2 < NC) { load_stage(sbase, (c + 2) % NSTAGE, c + 2, tid, Ag, Bg, m0, n0, K); cp_commit(); }
        if (c + 2 < NC)      cp_wait<2>();
        else if (c + 1 < NC) cp_wait<1>();
        else                 cp_wait<0>();
        __syncthreads();

        const uint32_t sa = sbase + (uint32_t)s * STG_SZ;
        const uint32_t sb = sa + STG_A;
        #pragma unroll
        for (int ks = 0; ks < 4; ks++) {
            const uint32_t koff = (uint32_t)((ks * 16 + (lane >> 4) * 8) * 2);
            uint32_t afr[4][4];
            #pragma unroll
            for (int mt = 0; mt < 4; mt++)
                ldsm_x4(afr[mt], sa + (wm + mt * 16 + (lane & 15)) * PITCH + koff);
            #pragma unroll
            for (int ntp = 0; ntp < 2; ntp++) {
                uint32_t q[4];
                ldsm_x4(q, sb + (wn + ntp * 16 + (lane & 15)) * PITCH + koff);
                uint32_t b0[2] = { q[0], q[2] };
                uint32_t b1[2] = { q[1], q[3] };
                #pragma unroll
                for (int mt = 0; mt < 4; mt++) {
                    mma16816(acc[mt][2 * ntp],     afr[mt], b0);
                    mma16816(acc[mt][2 * ntp + 1], afr[mt], b1);
                }
            }
        }
        __syncthreads();
    }

    #pragma unroll
    for (int mt = 0; mt < 4; mt++) {
        int r = m0 + wm + mt * 16 + (lane >> 2);
        #pragma unroll
        for (int nt = 0; nt < 4; nt++) {
            int col = n0 + wn + nt * 8 + (lane & 3) * 2;
            if (HALF_OUT) {
                __half* Cout = (__half*)CoutV;
                *reinterpret_cast<__half2*>(Cout + (size_t)r * N + col) =
                    __floats2half2_rn(acc[mt][nt][0], acc[mt][nt][1]);
                *reinterpret_cast<__half2*>(Cout + (size_t)(r + 8) * N + col) =
                    __floats2half2_rn(acc[mt][nt][2], acc[mt][nt][3]);
            } else {
                float* Cout = (float*)CoutV;
                __stcs(reinterpret_cast<float2*>(Cout + (size_t)r * N + col),
                       make_float2(acc[mt][nt][0], acc[mt][nt][1]));
                __stcs(reinterpret_cast<float2*>(Cout + (size_t)(r + 8) * N + col),
                       make_float2(acc[mt][nt][2], acc[mt][nt][3]));
            }
        }
    }
}

// ---------------- complex scan ----------------
__global__ void __launch_bounds__(256)
scan_local_kernel(const float* __restrict__ Amat, int bbase) {
    const int k = threadIdx.x;
    const int b = bbase + (blockIdx.x >> 7);
    const int chunk = blockIdx.x & (NCHUNK - 1);
    const float2 a = make_float2(Amat[k * 4 + 0], Amat[k * 4 + 1]);
    const __half2* w = reinterpret_cast<const __half2*>(g_uB)
                     + ((size_t)(b * LEN + chunk * CHUNK)) * KHALF + k;
    float2 z = make_float2(0.f, 0.f);
    #pragma unroll 8
    for (int j = 0; j < CHUNK; j++) {
        float2 wv = __half22float2(*w); w += KHALF;
        z = cmad(a, z, wv);
    }
    g_localF[(b * NCHUNK + chunk) * KHALF + k] = z;
}

__global__ void __launch_bounds__(32)
scan_carry_kernel(const float* __restrict__ Amat,
                  const float* __restrict__ x0, int bbase) {
    int idx = blockIdx.x * 32 + threadIdx.x;
    const int b = bbase + idx / KHALF, k = idx % KHALF;
    float2 a = make_float2(Amat[k * 4 + 0], Amat[k * 4 + 1]);
    float2 ac = a;
    #pragma unroll
    for (int i = 0; i < LOG2CHUNK; i++) ac = cmul(ac, ac);
    float2 z = make_float2(x0[(b * KHALF + k) * 2], x0[(b * KHALF + k) * 2 + 1]);
    g_carry[(b * NCHUNK + 0) * KHALF + k] = z;
    for (int g = 0; g < NCHUNK / 16; g++) {
        float2 F[16];
        #pragma unroll
        for (int j = 0; j < 16; j++) {
            int ix = g * 16 + j;
            F[j] = (ix < NCHUNK - 1) ? g_localF[(b * NCHUNK + ix) * KHALF + k]
                                     : make_float2(0.f, 0.f);
        }
        #pragma unroll
        for (int j = 0; j < 16; j++) {
            int cc = g * 16 + j + 1;
            if (cc < NCHUNK) { z = cmad(ac, z, F[j]); g_carry[(b * NCHUNK + cc) * KHALF + k] = z; }
        }
    }
}

__global__ void __launch_bounds__(256)
scan_final_kernel(const float* __restrict__ Amat,
                  float2* __restrict__ ns_out, int bbase) {
    const int k = threadIdx.x;
    const int b = bbase + (blockIdx.x >> 7);
    const int chunk = blockIdx.x & (NCHUNK - 1);
    const float2 a = make_float2(Amat[k * 4 + 0], Amat[k * 4 + 1]);
    float2 z = g_carry[(b * NCHUNK + chunk) * KHALF + k];
    const __half2* w = reinterpret_cast<const __half2*>(g_uB)
                     + ((size_t)(b * LEN + chunk * CHUNK)) * KHALF + k;
    __half2* xh = reinterpret_cast<__half2*>(g_xh)
                + ((size_t)(b * LEN + chunk * CHUNK)) * KHALF + k;
    #pragma unroll 8
    for (int j = 0; j < CHUNK; j++) {
        float2 wv = __half22float2(*w); w += KHALF;
        z = cmad(a, z, wv);
        *xh = __floats2half2_rn(z.x, z.y); xh += KHALF;
    }
    if (chunk == NCHUNK - 1) ns_out[b * KHALF + k] = z;
}

// ---------------- launch: staggered two-lane batch-split pipeline ----------------
extern "C" void kernel_launch(void* const* d_in, const int* in_sizes, int n_in,
                              void* d_out, int out_size) {
    const float* u  = (const float*)d_in[0];
    const float* x0 = (const float*)d_in[1];
    const float* A  = (const float*)d_in[2];
    const float* B  = (const float*)d_in[3];
    const float* C  = (const float*)d_in[4];
    const float* nw = (const float*)d_in[5];
    float* out = (float*)d_out;

    __half *d_uh, *d_xh, *d_Bt, *d_Ct, *d_uB;
    cudaGetSymbolAddress((void**)&d_uh, g_uh);
    cudaGetSymbolAddress((void**)&d_xh, g_xh);
    cudaGetSymbolAddress((void**)&d_Bt, g_Bt);
    cudaGetSymbolAddress((void**)&d_Ct, g_Ct);
    cudaGetSymbolAddress((void**)&d_uB, g_uB);

    cudaFuncSetAttribute(hgemm_kernel<true>,  cudaFuncAttributeMaxDynamicSharedMemorySize, SM_TOT);
    cudaFuncSetAttribute(hgemm_kernel<false>, cudaFuncAttributeMaxDynamicSharedMemorySize, SM_TOT);

    cudaStream_t s0 = 0;               // capture-origin stream: half 0 (lead lane)
    cudaStream_t s1 = g_aux.s1;        // forked lane: transposes + half 1
    float2* ns_out = reinterpret_cast<float2*>(out + (size_t)ROWS * OUTD);

    // fork s1 from s0
    cudaEventRecord(g_aux.eStart, s0);
    cudaStreamWaitEvent(s1, g_aux.eStart, 0);

    // s1: weight transposes (co-run with convert(h0) on s0; tiny)
    {
        dim3 blk(32, 8);
        dim3 gB(STATE / 32, INP / 32);
        transpose_kernel<<<gB, blk, 0, s1>>>(B, d_Bt, INP, STATE);
        dim3 gC(OUTD / 32, STATE / 32);
        transpose_kernel<<<gC, blk, 0, s1>>>(C, d_Ct, STATE, OUTD);
    }
    cudaEventRecord(g_aux.eT, s1);

    // ---- lane 0 (s0): convert(h0) at full bandwidth, then GEMM1(h0) ----
    convert_u_kernel<<<HROWS / 8, 256, 0, s0>>>(u, nw, 0);
    cudaEventRecord(g_aux.eC0, s0);        // release convert(h1)
    cudaStreamWaitEvent(s0, g_aux.eT, 0);  // GEMM1 needs Bt
    {
        dim3 grid(STATE / 128, HROWS / 128);
        hgemm_kernel<true><<<grid, 256, SM_TOT, s0>>>(d_uh, d_Bt, d_uB, INP, STATE, 0);
    }
    scan_local_kernel<<<HBATCH * NCHUNK, KHALF, 0, s0>>>(A, 0);
    scan_carry_kernel<<<HBATCH * KHALF / 32, 32, 0, s0>>>(A, x0, 0);
    scan_final_kernel<<<HBATCH * NCHUNK, KHALF, 0, s0>>>(A, ns_out, 0);
    {
        dim3 grid(OUTD / 128, HROWS / 128);
        hgemm_kernel<false><<<grid, 256, SM_TOT, s0>>>(d_xh, d_Ct, out, STATE, OUTD, 0);
    }

    // ---- lane 1 (s1): convert(h1) hides under GEMM1(h0), then its own chain ----
    cudaStreamWaitEvent(s1, g_aux.eC0, 0);   // stagger: don't share BW with convert(h0)
    convert_u_kernel<<<HROWS / 8, 256, 0, s1>>>(u, nw, HROWS);
    {
        dim3 grid(STATE / 128, HROWS / 128);
        hgemm_kernel<true><<<grid, 256, SM_TOT, s1>>>(d_uh, d_Bt, d_uB, INP, STATE, HROWS);
    }
    scan_local_kernel<<<HBATCH * NCHUNK, KHALF, 0, s1>>>(A, HBATCH);
    scan_carry_kernel<<<HBATCH * KHALF / 32, 32, 0, s1>>>(A, x0, HBATCH);
    scan_final_kernel<<<HBATCH * NCHUNK, KHALF, 0, s1>>>(A, ns_out, HBATCH);
    {
        dim3 grid(OUTD / 128, HROWS / 128);
        hgemm_kernel<false><<<grid, 256, SM_TOT, s1>>>(d_xh, d_Ct, out, STATE, OUTD, HROWS);
    }

    // join s1 back into s0
    cudaEventRecord(g_aux.eEnd, s1);
    cudaStreamWaitEvent(s0, g_aux.eEnd, 0);
}

// round 17
// speedup vs baseline: 1.0101x; 1.0101x over previous
#include <cuda_runtime.h>
#include <cuda_fp16.h>
#include <cstdint>
#include <math.h>

// ---------------- problem constants ----------------
#define BATCH 8
#define LEN   4096
#define INP   1024
#define STATE 512
#define KHALF 256
#define OUTD  1024
#define ROWS  (BATCH*LEN)      // 32768
#define HROWS (ROWS/2)         // 16384 (batch half)
#define HBATCH (BATCH/2)
#define CHUNK 32
#define NCHUNK (LEN/CHUNK)     // 128
#define LOG2CHUNK 5
#define EPSV 1e-6f

// ---------------- scratch (device globals; no runtime allocation) ----------------
__device__ __half g_uh[(size_t)ROWS * INP];      // rmsnormed u, fp16
__device__ __half g_uB[(size_t)ROWS * STATE];    // un @ B, fp16
__device__ __half g_xh[(size_t)ROWS * STATE];    // scan output, fp16
__device__ __half g_Bt[(size_t)STATE * INP];     // B^T  (512 x 1024)
__device__ __half g_Ct[(size_t)OUTD  * STATE];   // C^T  (1024 x 512)
__device__ float2 g_localF[BATCH * NCHUNK * KHALF];
__device__ float2 g_carry [BATCH * NCHUNK * KHALF];

// ---------------- one-time stream/event objects (host-side, pre-main) ----------
struct AuxStreams {
    cudaStream_t s1;
    cudaEvent_t eStart, eT, eEnd;
    AuxStreams() {
        cudaStreamCreateWithFlags(&s1, cudaStreamNonBlocking);
        cudaEventCreateWithFlags(&eStart, cudaEventDisableTiming);
        cudaEventCreateWithFlags(&eT,     cudaEventDisableTiming);
        cudaEventCreateWithFlags(&eEnd,   cudaEventDisableTiming);
    }
};
static AuxStreams g_aux;

// ---------------- helpers ----------------
__device__ __forceinline__ uint32_t smem_u32(const void* p) {
    uint32_t a;
    asm("{ .reg .u64 t; cvta.to.shared.u64 t, %1; cvt.u32.u64 %0, t; }" : "=r"(a) : "l"(p));
    return a;
}
__device__ __forceinline__ void cp16(uint32_t dst, const void* src) {
    asm volatile("cp.async.cg.shared.global [%0], [%1], 16;" :: "r"(dst), "l"(src));
}
__device__ __forceinline__ void cp_commit() { asm volatile("cp.async.commit_group;"); }
template <int N> __device__ __forceinline__ void cp_wait() {
    asm volatile("cp.async.wait_group %0;" :: "n"(N));
}
__device__ __forceinline__ void ldsm_x4(uint32_t* r, uint32_t addr) {
    asm volatile("ldmatrix.sync.aligned.m8n8.x4.shared.b16 {%0,%1,%2,%3}, [%4];"
                 : "=r"(r[0]), "=r"(r[1]), "=r"(r[2]), "=r"(r[3]) : "r"(addr));
}
__device__ __forceinline__ void mma16816(float* c, const uint32_t* a, const uint32_t* b) {
    asm volatile("mma.sync.aligned.m16n8k16.row.col.f32.f16.f16.f32 "
                 "{%0,%1,%2,%3}, {%4,%5,%6,%7}, {%8,%9}, {%0,%1,%2,%3};"
                 : "+f"(c[0]), "+f"(c[1]), "+f"(c[2]), "+f"(c[3])
                 : "r"(a[0]), "r"(a[1]), "r"(a[2]), "r"(a[3]), "r"(b[0]), "r"(b[1]));
}

// ---------------- complex helpers ----------------
__device__ __forceinline__ float2 cmul(float2 a, float2 b) {
    return make_float2(a.x * b.x - a.y * b.y, a.x * b.y + a.y * b.x);
}
__device__ __forceinline__ float2 cmad(float2 a, float2 z, float2 w) {
    return make_float2(fmaf(a.x, z.x, fmaf(-a.y, z.y, w.x)),
                       fmaf(a.x, z.y, fmaf( a.y, z.x, w.y)));
}

// ---------------- prep: fused rmsnorm -> fp16 u (warp-per-row) ----------------
__global__ void __launch_bounds__(256)
convert_u_kernel(const float* __restrict__ u, const float* __restrict__ nw, int row0) {
    const int row  = row0 + blockIdx.x * 8 + (threadIdx.x >> 5);
    const int lane = threadIdx.x & 31;
    const float4* up = reinterpret_cast<const float4*>(u) + (size_t)row * 256;
    float4 v[8];
    float s = 0.f;
    #pragma unroll
    for (int i = 0; i < 8; i++) {
        v[i] = __ldcs(up + lane + i * 32);
        s += v[i].x * v[i].x + v[i].y * v[i].y + v[i].z * v[i].z + v[i].w * v[i].w;
    }
    #pragma unroll
    for (int o = 16; o; o >>= 1) s += __shfl_xor_sync(0xffffffffu, s, o);
    const float rs = rsqrtf(s * (1.0f / INP) + EPSV);
    const float4* nwp = reinterpret_cast<const float4*>(nw);
    __half2* uh2 = reinterpret_cast<__half2*>(g_uh) + (size_t)row * 512;
    #pragma unroll
    for (int i = 0; i < 8; i++) {
        float4 w = nwp[lane + i * 32];
        int e = (lane + i * 32) * 2;
        uh2[e]     = __floats2half2_rn(v[i].x * rs * w.x, v[i].y * rs * w.y);
        uh2[e + 1] = __floats2half2_rn(v[i].z * rs * w.z, v[i].w * rs * w.w);
    }
}

// ---------------- prep: smem-tiled transpose float[M,N] -> half[N,M] ----------------
__global__ void __launch_bounds__(256)
transpose_kernel(const float* __restrict__ src, __half* __restrict__ dst,
                 int M, int N) {
    __shared__ float tile[32][33];
    const int n0 = blockIdx.x * 32;
    const int m0 = blockIdx.y * 32;
    #pragma unroll
    for (int i = 0; i < 4; i++) {
        int m = m0 + threadIdx.y + i * 8;
        tile[threadIdx.y + i * 8][threadIdx.x] = src[(size_t)m * N + n0 + threadIdx.x];
    }
    __syncthreads();
    #pragma unroll
    for (int i = 0; i < 4; i++) {
        int n = n0 + threadIdx.y + i * 8;
        dst[(size_t)n * M + m0 + threadIdx.x] =
            __float2half_rn(tile[threadIdx.x][threadIdx.y + i * 8]);
    }
}

// ---------------- HGEMM: C[M,N] = A[M,K](f16) x Bt[N,K](f16)^T ----------------
#define KCH     64
#define PITCH   144
#define STG_A   (128 * PITCH)
#define STG_SZ  (2 * STG_A)
#define NSTAGE  3
#define SM_TOT  (NSTAGE * STG_SZ)

__device__ __forceinline__ void load_stage(uint32_t sbase, int s, int c, int tid,
                                           const __half* __restrict__ Ag,
                                           const __half* __restrict__ Bg,
                                           int m0, int n0, int K) {
    const uint32_t sa = sbase + (uint32_t)s * STG_SZ;
    const uint32_t sb = sa + STG_A;
    #pragma unroll
    for (int i = 0; i < 4; i++) {
        int lin = tid + i * 256;
        int row = lin >> 3, ch = lin & 7;
        cp16(sa + row * PITCH + ch * 16, Ag + (size_t)(m0 + row) * K + c * KCH + ch * 8);
        cp16(sb + row * PITCH + ch * 16, Bg + (size_t)(n0 + row) * K + c * KCH + ch * 8);
    }
}

template <bool HALF_OUT>
__global__ void __launch_bounds__(256, 2)
hgemm_kernel(const __half* __restrict__ Ag, const __half* __restrict__ Bg,
             void* __restrict__ CoutV, int K, int N, int moff) {
    extern __shared__ char smem[];
    const uint32_t sbase = smem_u32(smem);
    const int tid  = threadIdx.x;
    const int lane = tid & 31;
    const int wid  = tid >> 5;
    const int wm   = (wid & 1) * 64;
    const int wn   = (wid >> 1) * 32;
    const int m0   = moff + blockIdx.y * 128;
    const int n0   = blockIdx.x * 128;
    const int NC   = K / KCH;

    float acc[4][4][4];
    #pragma unroll
    for (int i = 0; i < 4; i++)
        #pragma unroll
        for (int j = 0; j < 4; j++)
            #pragma unroll
            for (int q = 0; q < 4; q++) acc[i][j][q] = 0.f;

    load_stage(sbase, 0, 0, tid, Ag, Bg, m0, n0, K); cp_commit();
    load_stage(sbase, 1, 1, tid, Ag, Bg, m0, n0, K); cp_commit();

    for (int c = 0; c < NC; c++) {
        const int s = c % NSTAGE;
        if (c + 2 < NC) { load_stage(sbase, (c + 2) % NSTAGE, c + 2, tid, Ag, Bg, m0, n0, K); cp_commit(); }
        if (c + 2 < NC)      cp_wait<2>();
        else if (c + 1 < NC) cp_wait<1>();
        else                 cp_wait<0>();
        __syncthreads();

        const uint32_t sa = sbase + (uint32_t)s * STG_SZ;
        const uint32_t sb = sa + STG_A;
        #pragma unroll
        for (int ks = 0; ks < 4; ks++) {
            const uint32_t koff = (uint32_t)((ks * 16 + (lane >> 4) * 8) * 2);
            uint32_t afr[4][4];
            #pragma unroll
            for (int mt = 0; mt < 4; mt++)
                ldsm_x4(afr[mt], sa + (wm + mt * 16 + (lane & 15)) * PITCH + koff);
            #pragma unroll
            for (int ntp = 0; ntp < 2; ntp++) {
                uint32_t q[4];
                ldsm_x4(q, sb + (wn + ntp * 16 + (lane & 15)) * PITCH + koff);
                uint32_t b0[2] = { q[0], q[2] };
                uint32_t b1[2] = { q[1], q[3] };
                #pragma unroll
                for (int mt = 0; mt < 4; mt++) {
                    mma16816(acc[mt][2 * ntp],     afr[mt], b0);
                    mma16816(acc[mt][2 * ntp + 1], afr[mt], b1);
                }
            }
        }
        __syncthreads();
    }

    #pragma unroll
    for (int mt = 0; mt < 4; mt++) {
        int r = m0 + wm + mt * 16 + (lane >> 2);
        #pragma unroll
        for (int nt = 0; nt < 4; nt++) {
            int col = n0 + wn + nt * 8 + (lane & 3) * 2;
            if (HALF_OUT) {
                __half* Cout = (__half*)CoutV;
                *reinterpret_cast<__half2*>(Cout + (size_t)r * N + col) =
                    __floats2half2_rn(acc[mt][nt][0], acc[mt][nt][1]);
                *reinterpret_cast<__half2*>(Cout + (size_t)(r + 8) * N + col) =
                    __floats2half2_rn(acc[mt][nt][2], acc[mt][nt][3]);
            } else {
                float* Cout = (float*)CoutV;
                __stcs(reinterpret_cast<float2*>(Cout + (size_t)r * N + col),
                       make_float2(acc[mt][nt][0], acc[mt][nt][1]));
                __stcs(reinterpret_cast<float2*>(Cout + (size_t)(r + 8) * N + col),
                       make_float2(acc[mt][nt][2], acc[mt][nt][3]));
            }
        }
    }
}

// ---------------- complex scan ----------------
__global__ void __launch_bounds__(256)
scan_local_kernel(const float* __restrict__ Amat, int bbase) {
    const int k = threadIdx.x;
    const int b = bbase + (blockIdx.x >> 7);
    const int chunk = blockIdx.x & (NCHUNK - 1);
    const float2 a = make_float2(Amat[k * 4 + 0], Amat[k * 4 + 1]);
    const __half2* w = reinterpret_cast<const __half2*>(g_uB)
                     + ((size_t)(b * LEN + chunk * CHUNK)) * KHALF + k;
    float2 z = make_float2(0.f, 0.f);
    #pragma unroll 8
    for (int j = 0; j < CHUNK; j++) {
        float2 wv = __half22float2(*w); w += KHALF;
        z = cmad(a, z, wv);
    }
    g_localF[(b * NCHUNK + chunk) * KHALF + k] = z;
}

__global__ void __launch_bounds__(32)
scan_carry_kernel(const float* __restrict__ Amat,
                  const float* __restrict__ x0, int bbase) {
    int idx = blockIdx.x * 32 + threadIdx.x;
    const int b = bbase + idx / KHALF, k = idx % KHALF;
    float2 a = make_float2(Amat[k * 4 + 0], Amat[k * 4 + 1]);
    float2 ac = a;
    #pragma unroll
    for (int i = 0; i < LOG2CHUNK; i++) ac = cmul(ac, ac);
    float2 z = make_float2(x0[(b * KHALF + k) * 2], x0[(b * KHALF + k) * 2 + 1]);
    g_carry[(b * NCHUNK + 0) * KHALF + k] = z;
    for (int g = 0; g < NCHUNK / 16; g++) {
        float2 F[16];
        #pragma unroll
        for (int j = 0; j < 16; j++) {
            int ix = g * 16 + j;
            F[j] = (ix < NCHUNK - 1) ? g_localF[(b * NCHUNK + ix) * KHALF + k]
                                     : make_float2(0.f, 0.f);
        }
        #pragma unroll
        for (int j = 0; j < 16; j++) {
            int cc = g * 16 + j + 1;
            if (cc < NCHUNK) { z = cmad(ac, z, F[j]); g_carry[(b * NCHUNK + cc) * KHALF + k] = z; }
        }
    }
}

__global__ void __launch_bounds__(256)
scan_final_kernel(const float* __restrict__ Amat,
                  float2* __restrict__ ns_out, int bbase) {
    const int k = threadIdx.x;
    const int b = bbase + (blockIdx.x >> 7);
    const int chunk = blockIdx.x & (NCHUNK - 1);
    const float2 a = make_float2(Amat[k * 4 + 0], Amat[k * 4 + 1]);
    float2 z = g_carry[(b * NCHUNK + chunk) * KHALF + k];
    const __half2* w = reinterpret_cast<const __half2*>(g_uB)
                     + ((size_t)(b * LEN + chunk * CHUNK)) * KHALF + k;
    __half2* xh = reinterpret_cast<__half2*>(g_xh)
                + ((size_t)(b * LEN + chunk * CHUNK)) * KHALF + k;
    #pragma unroll 8
    for (int j = 0; j < CHUNK; j++) {
        float2 wv = __half22float2(__ldcs(w)); w += KHALF;   // last use of uB
        z = cmad(a, z, wv);
        *xh = __floats2half2_rn(z.x, z.y); xh += KHALF;
    }
    if (chunk == NCHUNK - 1) ns_out[b * KHALF + k] = z;
}

// ---------------- launch: two-lane batch-split pipeline (R15 + head fixes) ----------------
extern "C" void kernel_launch(void* const* d_in, const int* in_sizes, int n_in,
                              void* d_out, int out_size) {
    const float* u  = (const float*)d_in[0];
    const float* x0 = (const float*)d_in[1];
    const float* A  = (const float*)d_in[2];
    const float* B  = (const float*)d_in[3];
    const float* C  = (const float*)d_in[4];
    const float* nw = (const float*)d_in[5];
    float* out = (float*)d_out;

    __half *d_uh, *d_xh, *d_Bt, *d_Ct, *d_uB;
    cudaGetSymbolAddress((void**)&d_uh, g_uh);
    cudaGetSymbolAddress((void**)&d_xh, g_xh);
    cudaGetSymbolAddress((void**)&d_Bt, g_Bt);
    cudaGetSymbolAddress((void**)&d_Ct, g_Ct);
    cudaGetSymbolAddress((void**)&d_uB, g_uB);

    cudaFuncSetAttribute(hgemm_kernel<true>,  cudaFuncAttributeMaxDynamicSharedMemorySize, SM_TOT);
    cudaFuncSetAttribute(hgemm_kernel<false>, cudaFuncAttributeMaxDynamicSharedMemorySize, SM_TOT);

    cudaStream_t s0 = 0;               // capture-origin stream: half 0
    cudaStream_t s1 = g_aux.s1;        // forked lane: transposes + half 1
    float2* ns_out = reinterpret_cast<float2*>(out + (size_t)ROWS * OUTD);

    // fork s1 from s0
    cudaEventRecord(g_aux.eStart, s0);
    cudaStreamWaitEvent(s1, g_aux.eStart, 0);

    // s1: weight transposes first (off the head), then convert(h1) immediately
    {
        dim3 blk(32, 8);
        dim3 gB(STATE / 32, INP / 32);
        transpose_kernel<<<gB, blk, 0, s1>>>(B, d_Bt, INP, STATE);
        dim3 gC(OUTD / 32, STATE / 32);
        transpose_kernel<<<gC, blk, 0, s1>>>(C, d_Ct, STATE, OUTD);
    }
    cudaEventRecord(g_aux.eT, s1);
    convert_u_kernel<<<HROWS / 8, 256, 0, s1>>>(u, nw, HROWS);

    // ---- lane 0 (s0): convert(h0) at t0, then GEMM1(h0) (needs Bt) ----
    convert_u_kernel<<<HROWS / 8, 256, 0, s0>>>(u, nw, 0);
    cudaStreamWaitEvent(s0, g_aux.eT, 0);
    {
        dim3 grid(STATE / 128, HROWS / 128);
        hgemm_kernel<true><<<grid, 256, SM_TOT, s0>>>(d_uh, d_Bt, d_uB, INP, STATE, 0);
    }
    scan_local_kernel<<<HBATCH * NCHUNK, KHALF, 0, s0>>>(A, 0);
    scan_carry_kernel<<<HBATCH * KHALF / 32, 32, 0, s0>>>(A, x0, 0);
    scan_final_kernel<<<HBATCH * NCHUNK, KHALF, 0, s0>>>(A, ns_out, 0);
    {
        dim3 grid(OUTD / 128, HROWS / 128);
        hgemm_kernel<false><<<grid, 256, SM_TOT, s0>>>(d_xh, d_Ct, out, STATE, OUTD, 0);
    }

    // ---- lane 1 (s1): GEMM1(h1) then its own scan chain + GEMM2(h1) ----
    {
        dim3 grid(STATE / 128, HROWS / 128);
        hgemm_kernel<true><<<grid, 256, SM_TOT, s1>>>(d_uh, d_Bt, d_uB, INP, STATE, HROWS);
    }
    scan_local_kernel<<<HBATCH * NCHUNK, KHALF, 0, s1>>>(A, HBATCH);
    scan_carry_kernel<<<HBATCH * KHALF / 32, 32, 0, s1>>>(A, x0, HBATCH);
    scan_final_kernel<<<HBATCH * NCHUNK, KHALF, 0, s1>>>(A, ns_out, HBATCH);
    {
        dim3 grid(OUTD / 128, HROWS / 128);
        hgemm_kernel<false><<<grid, 256, SM_TOT, s1>>>(d_xh, d_Ct, out, STATE, OUTD, HROWS);
    }

    // join s1 back into s0
    cudaEventRecord(g_aux.eEnd, s1);
    cudaStreamWaitEvent(s0, g_aux.eEnd, 0);
}